// round 16
// baseline (speedup 1.0000x reference)
#include <cuda_runtime.h>
#include <cuda_bf16.h>
#include <math.h>
#include <stdint.h>

// Problem dims (fixed by the reference)
#define NB 256            // batch
#define NT 128            // seq len
#define ND 512            // embed dim
#define NS 256            // shrink dim
#define NM (NB*NT)        // 32768 flattened (t,b) rows

#define SGRID 128         // step kernel CTAs: 16 chains x 8 n-blocks (cluster=chain)
#define PROW 260          // padded smem row in bf16-PAIRS (256 + 4)
// Ws0[64] Ws1[64] | hb0: s0[16] s1[16] | hb1: s0[16] s1[16]  (rows of PROW u32)
// + 2 mbarriers
#define STEP_SMEM ((192*PROW)*4 + 64)

// ---------------------------------------------------------------------------
// Scratch (device globals; no runtime allocation allowed)
// ---------------------------------------------------------------------------
__device__ float g_C1[(size_t)NM * NS];     // relu(E @ W_inp^T + b_inp)
__device__ float g_L [(size_t)NM * ND];     // relu(C1 @ W_mid^T + b_mid)  [t][b][512]
__device__ float g_hfin[(size_t)NB * ND];   // final h (fp32) for norm

// ---------------------------------------------------------------------------
// mma / ldmatrix / cluster helpers
// ---------------------------------------------------------------------------
__device__ __forceinline__ uint32_t f2tf(float f)
{
    uint32_t u;
    asm("cvt.rna.tf32.f32 %0, %1;" : "=r"(u) : "f"(f));
    return u;
}

__device__ __forceinline__ void mma_tf32(float d[4], const uint32_t a[4], const uint32_t b[2])
{
    asm volatile(
        "mma.sync.aligned.m16n8k8.row.col.f32.tf32.tf32.f32 "
        "{%0,%1,%2,%3}, {%4,%5,%6,%7}, {%8,%9}, {%0,%1,%2,%3};"
        : "+f"(d[0]), "+f"(d[1]), "+f"(d[2]), "+f"(d[3])
        : "r"(a[0]), "r"(a[1]), "r"(a[2]), "r"(a[3]), "r"(b[0]), "r"(b[1]));
}

__device__ __forceinline__ void mma_bf16(float d[4], const uint32_t a[4], const uint32_t b[2])
{
    asm volatile(
        "mma.sync.aligned.m16n8k16.row.col.f32.bf16.bf16.f32 "
        "{%0,%1,%2,%3}, {%4,%5,%6,%7}, {%8,%9}, {%0,%1,%2,%3};"
        : "+f"(d[0]), "+f"(d[1]), "+f"(d[2]), "+f"(d[3])
        : "r"(a[0]), "r"(a[1]), "r"(a[2]), "r"(a[3]), "r"(b[0]), "r"(b[1]));
}

__device__ __forceinline__ void ldsm_x4(uint32_t r[4], uint32_t addr)
{
    asm volatile("ldmatrix.sync.aligned.m8n8.x4.shared.b16 {%0,%1,%2,%3}, [%4];"
        : "=r"(r[0]), "=r"(r[1]), "=r"(r[2]), "=r"(r[3]) : "r"(addr));
}

__device__ __forceinline__ uint32_t smem_u32(const void* p)
{
    return (uint32_t)__cvta_generic_to_shared(p);
}

__device__ __forceinline__ uint32_t mapa_rank(uint32_t addr, int rank)
{
    uint32_t r;
    asm("mapa.shared::cluster.u32 %0, %1, %2;" : "=r"(r) : "r"(addr), "r"(rank));
    return r;
}

__device__ __forceinline__ void st_cluster_u32(uint32_t addr, uint32_t v)
{
    asm volatile("st.shared::cluster.u32 [%0], %1;" :: "r"(addr), "r"(v) : "memory");
}

__device__ __forceinline__ void bar_arrive_remote(uint32_t bar, int rank)
{
    asm volatile(
        "{\n\t"
        ".reg .b32 r;\n\t"
        "mapa.shared::cluster.u32 r, %0, %1;\n\t"
        "mbarrier.arrive.release.cluster.shared::cluster.b64 _, [r];\n\t"
        "}" :: "r"(bar), "r"(rank) : "memory");
}

__device__ __forceinline__ void bar_wait_cluster(uint32_t bar, int parity)
{
    asm volatile(
        "{\n\t"
        ".reg .pred P;\n\t"
        "WL_%=:\n\t"
        "mbarrier.try_wait.parity.acquire.cluster.shared::cta.b64 P, [%0], %1;\n\t"
        "@!P bra WL_%=;\n\t"
        "}" :: "r"(bar), "r"(parity) : "memory");
}

// ---------------------------------------------------------------------------
// FF GEMMs (tf32 tensor cores, validated since R4)
// ---------------------------------------------------------------------------
__global__ __launch_bounds__(256, 2) void gemm1_kernel(
    const int*   __restrict__ x,
    const float* __restrict__ emb,
    const float* __restrict__ W,     // [NS][ND]
    const float* __restrict__ bias)  // [NS]
{
    __shared__ __align__(16) uint32_t As[128][36];
    __shared__ __align__(16) uint32_t Bs[128][36];

    const int tid  = threadIdx.x;
    const int warp = tid >> 5;
    const int lane = tid & 31;
    const int m0c  = blockIdx.y * 128;
    const int n0c  = blockIdx.x * 128;

    const int row = tid >> 1;
    const int kq  = tid & 1;

    const int m   = m0c + row;
    const int bb_ = m & (NB - 1);
    const int tt_ = m >> 8;
    const int tok = x[bb_ * NT + tt_];
    const bool az = (tok == 0);
    const float* arow = emb + (size_t)tok * ND;
    const float* brow = W   + (size_t)(n0c + row) * ND;

    const int wm = (warp & 1) * 64;
    const int wn = (warp >> 1) * 32;
    const int ly = lane >> 2;
    const int lx = lane & 3;

    float acc[4][4][4] = {};

    float4 pa[4], pb[4];
#pragma unroll
    for (int q = 0; q < 4; q++) {
        pa[q] = az ? make_float4(0.f,0.f,0.f,0.f) : *(const float4*)&arow[kq*16 + q*4];
        pb[q] = *(const float4*)&brow[kq*16 + q*4];
    }

    for (int k0 = 0; k0 < ND; k0 += 32) {
#pragma unroll
        for (int q = 0; q < 4; q++) {
            const int c = kq*16 + q*4;
            *(uint4*)&As[row][c] = make_uint4(f2tf(pa[q].x), f2tf(pa[q].y), f2tf(pa[q].z), f2tf(pa[q].w));
            *(uint4*)&Bs[row][c] = make_uint4(f2tf(pb[q].x), f2tf(pb[q].y), f2tf(pb[q].z), f2tf(pb[q].w));
        }
        __syncthreads();
        if (k0 + 32 < ND) {
#pragma unroll
            for (int q = 0; q < 4; q++) {
                pa[q] = az ? make_float4(0.f,0.f,0.f,0.f) : *(const float4*)&arow[k0+32 + kq*16 + q*4];
                pb[q] = *(const float4*)&brow[k0+32 + kq*16 + q*4];
            }
        }
#pragma unroll
        for (int kk = 0; kk < 4; kk++) {
            const int kb = kk * 8;
            uint32_t af[4][4], bf[4][2];
#pragma unroll
            for (int mf = 0; mf < 4; mf++) {
                const int rb = wm + mf*16 + ly;
                af[mf][0] = As[rb    ][kb + lx];
                af[mf][1] = As[rb + 8][kb + lx];
                af[mf][2] = As[rb    ][kb + lx + 4];
                af[mf][3] = As[rb + 8][kb + lx + 4];
            }
#pragma unroll
            for (int nf = 0; nf < 4; nf++) {
                const int nb = wn + nf*8 + ly;
                bf[nf][0] = Bs[nb][kb + lx];
                bf[nf][1] = Bs[nb][kb + lx + 4];
            }
#pragma unroll
            for (int mf = 0; mf < 4; mf++)
#pragma unroll
                for (int nf = 0; nf < 4; nf++)
                    mma_tf32(acc[mf][nf], af[mf], bf[nf]);
        }
        __syncthreads();
    }

#pragma unroll
    for (int nf = 0; nf < 4; nf++) {
        const int gn = n0c + wn + nf*8 + lx*2;
        const float2 bv = *(const float2*)&bias[gn];
#pragma unroll
        for (int mf = 0; mf < 4; mf++) {
            const int gm0 = m0c + wm + mf*16 + ly;
            float2 o0, o1;
            o0.x = fmaxf(acc[mf][nf][0] + bv.x, 0.f);
            o0.y = fmaxf(acc[mf][nf][1] + bv.y, 0.f);
            o1.x = fmaxf(acc[mf][nf][2] + bv.x, 0.f);
            o1.y = fmaxf(acc[mf][nf][3] + bv.y, 0.f);
            *(float2*)&g_C1[(size_t)gm0*NS + gn]       = o0;
            *(float2*)&g_C1[(size_t)(gm0+8)*NS + gn]   = o1;
        }
    }
}

__global__ __launch_bounds__(256, 2) void gemm2_kernel(
    const float* __restrict__ W,     // [ND][NS]
    const float* __restrict__ bias)  // [ND]
{
    __shared__ __align__(16) uint32_t As[128][36];
    __shared__ __align__(16) uint32_t Bs[128][36];

    const int tid  = threadIdx.x;
    const int warp = tid >> 5;
    const int lane = tid & 31;
    const int m0c  = blockIdx.y * 128;
    const int n0c  = blockIdx.x * 128;

    const int row = tid >> 1;
    const int kq  = tid & 1;

    const float* arow = g_C1 + (size_t)(m0c + row) * NS;
    const float* brow = W    + (size_t)(n0c + row) * NS;

    const int wm = (warp & 1) * 64;
    const int wn = (warp >> 1) * 32;
    const int ly = lane >> 2;
    const int lx = lane & 3;

    float acc[4][4][4] = {};

    float4 pa[4], pb[4];
#pragma unroll
    for (int q = 0; q < 4; q++) {
        pa[q] = *(const float4*)&arow[kq*16 + q*4];
        pb[q] = *(const float4*)&brow[kq*16 + q*4];
    }

    for (int k0 = 0; k0 < NS; k0 += 32) {
#pragma unroll
        for (int q = 0; q < 4; q++) {
            const int c = kq*16 + q*4;
            *(uint4*)&As[row][c] = make_uint4(f2tf(pa[q].x), f2tf(pa[q].y), f2tf(pa[q].z), f2tf(pa[q].w));
            *(uint4*)&Bs[row][c] = make_uint4(f2tf(pb[q].x), f2tf(pb[q].y), f2tf(pb[q].z), f2tf(pb[q].w));
        }
        __syncthreads();
        if (k0 + 32 < NS) {
#pragma unroll
            for (int q = 0; q < 4; q++) {
                pa[q] = *(const float4*)&arow[k0+32 + kq*16 + q*4];
                pb[q] = *(const float4*)&brow[k0+32 + kq*16 + q*4];
            }
        }
#pragma unroll
        for (int kk = 0; kk < 4; kk++) {
            const int kb = kk * 8;
            uint32_t af[4][4], bf[4][2];
#pragma unroll
            for (int mf = 0; mf < 4; mf++) {
                const int rb = wm + mf*16 + ly;
                af[mf][0] = As[rb    ][kb + lx];
                af[mf][1] = As[rb + 8][kb + lx];
                af[mf][2] = As[rb    ][kb + lx + 4];
                af[mf][3] = As[rb + 8][kb + lx + 4];
            }
#pragma unroll
            for (int nf = 0; nf < 4; nf++) {
                const int nb = wn + nf*8 + ly;
                bf[nf][0] = Bs[nb][kb + lx];
                bf[nf][1] = Bs[nb][kb + lx + 4];
            }
#pragma unroll
            for (int mf = 0; mf < 4; mf++)
#pragma unroll
                for (int nf = 0; nf < 4; nf++)
                    mma_tf32(acc[mf][nf], af[mf], bf[nf]);
        }
        __syncthreads();
    }

#pragma unroll
    for (int nf = 0; nf < 4; nf++) {
        const int gn = n0c + wn + nf*8 + lx*2;
        const float2 bv = *(const float2*)&bias[gn];
#pragma unroll
        for (int mf = 0; mf < 4; mf++) {
            const int gm0 = m0c + wm + mf*16 + ly;
            float2 o0, o1;
            o0.x = fmaxf(acc[mf][nf][0] + bv.x, 0.f);
            o0.y = fmaxf(acc[mf][nf][1] + bv.y, 0.f);
            o1.x = fmaxf(acc[mf][nf][2] + bv.x, 0.f);
            o1.y = fmaxf(acc[mf][nf][3] + bv.y, 0.f);
            *(float2*)&g_L[(size_t)gm0*ND + gn]       = o0;
            *(float2*)&g_L[(size_t)(gm0+8)*ND + gn]   = o1;
        }
    }
}

// ---------------------------------------------------------------------------
// Persistent recurrent kernel — DSMEM push + mbarrier (cluster = chain).
// 128 CTAs = 16 chains x 8 n-blocks, cluster(8). CTA tile 16(M) x 64(N).
// h never touches global: each CTA scatters its bf16-pair chunk into all 8
// peers' double-buffered smem (st.shared::cluster) and arrives on their
// mbarriers (release.cluster). Consumer: tid0 try_wait.acquire.cluster,
// then mma straight from smem (no staging pass). Final h stored fp32.
// ---------------------------------------------------------------------------
__global__ __launch_bounds__(256, 1) __cluster_dims__(8, 1, 1)
void step_persist(
    const float* __restrict__ Wh,     // [ND][ND]
    const float* __restrict__ bhid)   // [ND]
{
    extern __shared__ uint32_t smu[]; // bf16 PAIRS, row stride PROW
    uint32_t* Ws0 = smu;              // [64][PROW] W main
    uint32_t* Ws1 = smu + 64*PROW;    // [64][PROW] W residual
    // hb[b]: s0 at (128 + 32b)*PROW, s1 at +16*PROW

    const uint32_t smem0   = smem_u32(smu);
    const uint32_t barBase = smem0 + (uint32_t)(192*PROW)*4;   // 2 x u64 mbarriers

    const int tid  = threadIdx.x;
    const int bx   = blockIdx.x;
    const int mb   = bx >> 3;          // chain id
    const int rank = bx & 7;           // n-block within chain (== cluster rank)
    const int m0   = mb * 16;
    const int n0   = rank * 64;
    const int warp = tid >> 5;
    const int lane = tid & 31;
    const int wn   = warp * 8;
    const int ly   = lane >> 2;
    const int lx   = lane & 3;

    // --- split W slice [64n][512k] into bf16 hi/lo pairs in smem (once) ---
#pragma unroll
    for (int i = 0; i < 64; i++) {
        const int idx = tid + i*256;
        const int r   = idx >> 8;
        const int p   = idx & 255;
        float2 w = *(const float2*)&Wh[(size_t)(n0+r)*ND + p*2];
        __nv_bfloat16 h0x = __float2bfloat16_rn(w.x);
        __nv_bfloat16 h0y = __float2bfloat16_rn(w.y);
        float rx = w.x - __bfloat162float(h0x);
        float ry = w.y - __bfloat162float(h0y);
        __nv_bfloat162 p0; p0.x = h0x; p0.y = h0y;
        __nv_bfloat162 p1; p1.x = __float2bfloat16_rn(rx); p1.y = __float2bfloat16_rn(ry);
        Ws0[r*PROW + p] = *(uint32_t*)&p0;
        Ws1[r*PROW + p] = *(uint32_t*)&p1;
    }
    const int gnc = n0 + wn + lx*2;
    const float bb0 = bhid[gnc];
    const float bb1 = bhid[gnc + 1];
    const int gm0 = m0 + ly;               // output rows gm0, gm0+8

    // ldmatrix base addresses for both h buffers
    const uint32_t aOff = (uint32_t)((lane & 15) * PROW * 4 + (lane >> 4) * 16);
    const uint32_t aHiB[2] = { smem0 + (uint32_t)(128*PROW)*4 + aOff,
                               smem0 + (uint32_t)(160*PROW)*4 + aOff };
    // s1 = s0 + 16*PROW u32
    const uint32_t bOff = (uint32_t)((wn + (lane & 7)) * PROW * 4 + (lane >> 3) * 16);
    const uint32_t bHi  = smem_u32(Ws0) + bOff;
    const uint32_t bLo  = smem_u32(Ws1) + bOff;

    // scatter bases: my data position in any consumer's hb0.s0
    const int pcol = rank*32 + (wn >> 1) + lx;     // pair column in [0,256)
    const uint32_t scat_local = smem0 + (uint32_t)(128*PROW + ly*PROW + pcol)*4;
    uint32_t scat_base[8];
#pragma unroll
    for (int k = 0; k < 8; k++) scat_base[k] = mapa_rank(scat_local, k);

    // init mbarriers (count = 8 producers per phase), then cluster-wide sync
    if (tid == 0) {
        asm volatile("mbarrier.init.shared.b64 [%0], 8;" :: "r"(barBase)     : "memory");
        asm volatile("mbarrier.init.shared.b64 [%0], 8;" :: "r"(barBase + 8) : "memory");
    }
    __syncthreads();
    asm volatile("barrier.cluster.arrive.aligned;" ::: "memory");
    asm volatile("barrier.cluster.wait.aligned;"   ::: "memory");

    int ph[2] = {0, 0};

    // prefetch L for t=0
    float2 l0 = __ldg((const float2*)&g_L[(size_t)gm0*ND + gnc]);
    float2 l1 = __ldg((const float2*)&g_L[(size_t)(gm0+8)*ND + gnc]);

    for (int t = 0; t < NT; t++) {
        const int b   = t & 1;
        const int nb2 = (t + 1) & 1;

        float acc[4] = {0.f, 0.f, 0.f, 0.f};
        if (t > 0) {
            // wait: all 8 producers deposited h(t) into my hb[b]
            if (tid == 0) bar_wait_cluster(barBase + b*8, ph[b]);
            ph[b] ^= 1;
            __syncthreads();

            const uint32_t aHi = aHiB[b];
            const uint32_t aLo = aHi + (uint32_t)(16*PROW)*4;
#pragma unroll 4
            for (int kc = 0; kc < 16; kc++) {
                const uint32_t off = kc * 64;
                uint32_t ah0[4], ah1[4], al0[4], al1[4], bh[4], bl[4];
                ldsm_x4(ah0, aHi + off);
                ldsm_x4(ah1, aHi + off + 32);
                ldsm_x4(al0, aLo + off);
                ldsm_x4(al1, aLo + off + 32);
                ldsm_x4(bh,  bHi + off);
                ldsm_x4(bl,  bLo + off);
                mma_bf16(acc, ah0, &bh[0]);
                mma_bf16(acc, al0, &bh[0]);
                mma_bf16(acc, ah0, &bl[0]);
                mma_bf16(acc, ah1, &bh[2]);
                mma_bf16(acc, al1, &bh[2]);
                mma_bf16(acc, ah1, &bl[2]);
            }
        }

        // epilogue: +L +bias, tanh, bf16 split, DSMEM scatter to all 8 peers
        {
            float o00 = tanhf(acc[0] + l0.x + bb0);
            float o01 = tanhf(acc[1] + l0.y + bb1);
            float o10 = tanhf(acc[2] + l1.x + bb0);
            float o11 = tanhf(acc[3] + l1.y + bb1);

            if (t == NT - 1) {
                *(float2*)&g_hfin[(size_t)gm0*ND + gnc]     = make_float2(o00, o01);
                *(float2*)&g_hfin[(size_t)(gm0+8)*ND + gnc] = make_float2(o10, o11);
            } else {
                __nv_bfloat162 h00, h01, r00, r01;
                h00.x = __float2bfloat16_rn(o00);
                h00.y = __float2bfloat16_rn(o01);
                r00.x = __float2bfloat16_rn(o00 - __bfloat162float(h00.x));
                r00.y = __float2bfloat16_rn(o01 - __bfloat162float(h00.y));
                h01.x = __float2bfloat16_rn(o10);
                h01.y = __float2bfloat16_rn(o11);
                r01.x = __float2bfloat16_rn(o10 - __bfloat162float(h01.x));
                r01.y = __float2bfloat16_rn(o11 - __bfloat162float(h01.y));
                const uint32_t u_h00 = *(uint32_t*)&h00;
                const uint32_t u_h01 = *(uint32_t*)&h01;
                const uint32_t u_r00 = *(uint32_t*)&r00;
                const uint32_t u_r01 = *(uint32_t*)&r01;
                const uint32_t bo = (uint32_t)nb2 * (uint32_t)(32*PROW)*4;
#pragma unroll
                for (int k = 0; k < 8; k++) {
                    const uint32_t a = scat_base[k] + bo;
                    st_cluster_u32(a,                           u_h00);  // s0 row ly
                    st_cluster_u32(a + (uint32_t)( 8*PROW)*4,   u_h01);  // s0 row ly+8
                    st_cluster_u32(a + (uint32_t)(16*PROW)*4,   u_r00);  // s1 row ly
                    st_cluster_u32(a + (uint32_t)(24*PROW)*4,   u_r01);  // s1 row ly+8
                }
            }
        }

        // prefetch L for t+1 (overlaps arrive propagation / next wait)
        if (t + 1 < NT) {
            const float* __restrict__ Ln = g_L + (size_t)(t+1) * NB * ND;
            l0 = __ldg((const float2*)&Ln[(size_t)gm0*ND + gnc]);
            l1 = __ldg((const float2*)&Ln[(size_t)(gm0+8)*ND + gnc]);
        }

        // publish: syncthreads (CTA HB into tid0), then release-arrive on all
        // peers' bar[nb2] (cumulativity covers all threads' DSMEM stores)
        if (t + 1 < NT) {
            __syncthreads();
            if (tid == 0) {
#pragma unroll
                for (int k = 0; k < 8; k++)
                    bar_arrive_remote(barBase + nb2*8, k);
            }
        }
    }

    // no CTA may exit while peers' DSMEM traffic may still target its smem
    asm volatile("barrier.cluster.arrive.aligned;" ::: "memory");
    asm volatile("barrier.cluster.wait.aligned;"   ::: "memory");
}

// ---------------------------------------------------------------------------
// Row L2-normalize final h (fp32 buffer)
// ---------------------------------------------------------------------------
__global__ __launch_bounds__(128) void norm_kernel(float* __restrict__ out)
{
    __shared__ float red[4];
    const int row = blockIdx.x;
    const int tid = threadIdx.x;   // each covers 4 cols

    const float* h = g_hfin + (size_t)row * ND;
    float4 v = *(const float4*)&h[tid * 4];
    float s = v.x*v.x + v.y*v.y + v.z*v.z + v.w*v.w;
#pragma unroll
    for (int o = 16; o; o >>= 1) s += __shfl_xor_sync(0xFFFFFFFFu, s, o);
    if ((tid & 31) == 0) red[tid >> 5] = s;
    __syncthreads();
    const float tot = red[0] + red[1] + red[2] + red[3];
    const float inv = 1.f / fmaxf(sqrtf(tot), 1e-12f);
    float4 o4 = make_float4(v.x*inv, v.y*inv, v.z*inv, v.w*inv);
    *(float4*)&out[(size_t)row * ND + tid * 4] = o4;
}

// ---------------------------------------------------------------------------
// Launch
// ---------------------------------------------------------------------------
extern "C" void kernel_launch(void* const* d_in, const int* in_sizes, int n_in,
                              void* d_out, int out_size)
{
    const int*   x     = (const int*)  d_in[0];
    const float* emb   = (const float*)d_in[1];
    const float* W_inp = (const float*)d_in[2];
    const float* b_inp = (const float*)d_in[3];
    const float* W_mid = (const float*)d_in[4];
    const float* b_mid = (const float*)d_in[5];
    const float* W_hid = (const float*)d_in[6];
    const float* b_hid = (const float*)d_in[7];
    float* out = (float*)d_out;

    cudaFuncSetAttribute(step_persist, cudaFuncAttributeMaxDynamicSharedMemorySize, STEP_SMEM);

    // Feed-forward part for ALL timesteps (tensor cores, tf32)
    gemm1_kernel<<<dim3(NS/128, NM/128), 256>>>(x, emb, W_inp, b_inp);
    gemm2_kernel<<<dim3(ND/128, NM/128), 256>>>(W_mid, b_mid);

    // Recurrence: persistent cluster kernel, DSMEM h exchange + mbarriers
    step_persist<<<SGRID, 256, STEP_SMEM>>>(W_hid, b_hid);

    norm_kernel<<<NB, 128>>>(out);
}

// round 17
// speedup vs baseline: 2.3228x; 2.3228x over previous
#include <cuda_runtime.h>
#include <cuda_bf16.h>
#include <math.h>
#include <stdint.h>

// Problem dims (fixed by the reference)
#define NB 256            // batch
#define NT 128            // seq len
#define ND 512            // embed dim
#define NS 256            // shrink dim
#define NM (NB*NT)        // 32768 flattened (t,b) rows

#define SGRID 128         // step kernel CTAs: 16 m-chains x 8 n-blocks
#define PROW 260          // padded smem row in bf16-PAIRS (256 + 4)
// Ws0[64][PROW] + Ws1[64][PROW] + hs0[16][PROW] + hs1[16][PROW] uint32
#define STEP_SMEM ((2*64 + 2*16) * PROW * 4)

// ---------------------------------------------------------------------------
// Scratch (device globals; no runtime allocation allowed)
// ---------------------------------------------------------------------------
__device__ float g_C1[(size_t)NM * NS];     // relu(E @ W_inp^T + b_inp)
__device__ float g_L [(size_t)NM * ND];     // relu(C1 @ W_mid^T + b_mid)  [t][b][512]
__device__ __nv_bfloat16 g_h0[2][(size_t)NB * ND];  // h main part (bf16), ping-pong
__device__ __nv_bfloat16 g_h1[2][(size_t)NB * ND];  // h residual part (bf16)
__device__ unsigned g_flag[16];             // per-m-chain step counters (8 producers each)
__device__ unsigned g_c1flag[256];          // per-128-row C1 block (2 producers)

// ---------------------------------------------------------------------------
// mma / ldmatrix / sync helpers
// ---------------------------------------------------------------------------
__device__ __forceinline__ uint32_t f2tf(float f)
{
    uint32_t u;
    asm("cvt.rna.tf32.f32 %0, %1;" : "=r"(u) : "f"(f));
    return u;
}

__device__ __forceinline__ void mma_tf32(float d[4], const uint32_t a[4], const uint32_t b[2])
{
    asm volatile(
        "mma.sync.aligned.m16n8k8.row.col.f32.tf32.tf32.f32 "
        "{%0,%1,%2,%3}, {%4,%5,%6,%7}, {%8,%9}, {%0,%1,%2,%3};"
        : "+f"(d[0]), "+f"(d[1]), "+f"(d[2]), "+f"(d[3])
        : "r"(a[0]), "r"(a[1]), "r"(a[2]), "r"(a[3]), "r"(b[0]), "r"(b[1]));
}

__device__ __forceinline__ void mma_bf16(float d[4], const uint32_t a[4], const uint32_t b[2])
{
    asm volatile(
        "mma.sync.aligned.m16n8k16.row.col.f32.bf16.bf16.f32 "
        "{%0,%1,%2,%3}, {%4,%5,%6,%7}, {%8,%9}, {%0,%1,%2,%3};"
        : "+f"(d[0]), "+f"(d[1]), "+f"(d[2]), "+f"(d[3])
        : "r"(a[0]), "r"(a[1]), "r"(a[2]), "r"(a[3]), "r"(b[0]), "r"(b[1]));
}

__device__ __forceinline__ void ldsm_x4(uint32_t r[4], uint32_t addr)
{
    asm volatile("ldmatrix.sync.aligned.m8n8.x4.shared.b16 {%0,%1,%2,%3}, [%4];"
        : "=r"(r[0]), "=r"(r[1]), "=r"(r[2]), "=r"(r[3]) : "r"(addr));
}

__device__ __forceinline__ uint32_t smem_u32(const void* p)
{
    return (uint32_t)__cvta_generic_to_shared(p);
}

__device__ __forceinline__ unsigned ld_acquire_gpu(const unsigned* p)
{
    unsigned v;
    asm volatile("ld.acquire.gpu.global.u32 %0, [%1];" : "=r"(v) : "l"(p) : "memory");
    return v;
}

__device__ __forceinline__ void pdl_trigger()
{
    asm volatile("griddepcontrol.launch_dependents;");
}

// ---------------------------------------------------------------------------
// FF GEMMs (tf32 tensor cores, validated since R4).
// gemm1 triggers PDL + publishes per-block flags; gemm2 launches dependent
// and waits on them, overlapping the two GEMMs. step launches normally.
// ---------------------------------------------------------------------------
__global__ __launch_bounds__(256, 2) void gemm1_kernel(
    const int*   __restrict__ x,
    const float* __restrict__ emb,
    const float* __restrict__ W,     // [NS][ND]
    const float* __restrict__ bias)  // [NS]
{
    __shared__ __align__(16) uint32_t As[128][36];
    __shared__ __align__(16) uint32_t Bs[128][36];

    const int tid  = threadIdx.x;
    const int warp = tid >> 5;
    const int lane = tid & 31;
    const int m0c  = blockIdx.y * 128;
    const int n0c  = blockIdx.x * 128;

    if (tid == 0) pdl_trigger();    // allow gemm2 to co-schedule

    const int row = tid >> 1;
    const int kq  = tid & 1;

    const int m   = m0c + row;
    const int bb_ = m & (NB - 1);
    const int tt_ = m >> 8;
    const int tok = x[bb_ * NT + tt_];
    const bool az = (tok == 0);
    const float* arow = emb + (size_t)tok * ND;
    const float* brow = W   + (size_t)(n0c + row) * ND;

    const int wm = (warp & 1) * 64;
    const int wn = (warp >> 1) * 32;
    const int ly = lane >> 2;
    const int lx = lane & 3;

    float acc[4][4][4] = {};

    float4 pa[4], pb[4];
#pragma unroll
    for (int q = 0; q < 4; q++) {
        pa[q] = az ? make_float4(0.f,0.f,0.f,0.f) : *(const float4*)&arow[kq*16 + q*4];
        pb[q] = *(const float4*)&brow[kq*16 + q*4];
    }

    for (int k0 = 0; k0 < ND; k0 += 32) {
#pragma unroll
        for (int q = 0; q < 4; q++) {
            const int c = kq*16 + q*4;
            *(uint4*)&As[row][c] = make_uint4(f2tf(pa[q].x), f2tf(pa[q].y), f2tf(pa[q].z), f2tf(pa[q].w));
            *(uint4*)&Bs[row][c] = make_uint4(f2tf(pb[q].x), f2tf(pb[q].y), f2tf(pb[q].z), f2tf(pb[q].w));
        }
        __syncthreads();
        if (k0 + 32 < ND) {
#pragma unroll
            for (int q = 0; q < 4; q++) {
                pa[q] = az ? make_float4(0.f,0.f,0.f,0.f) : *(const float4*)&arow[k0+32 + kq*16 + q*4];
                pb[q] = *(const float4*)&brow[k0+32 + kq*16 + q*4];
            }
        }
#pragma unroll
        for (int kk = 0; kk < 4; kk++) {
            const int kb = kk * 8;
            uint32_t af[4][4], bf[4][2];
#pragma unroll
            for (int mf = 0; mf < 4; mf++) {
                const int rb = wm + mf*16 + ly;
                af[mf][0] = As[rb    ][kb + lx];
                af[mf][1] = As[rb + 8][kb + lx];
                af[mf][2] = As[rb    ][kb + lx + 4];
                af[mf][3] = As[rb + 8][kb + lx + 4];
            }
#pragma unroll
            for (int nf = 0; nf < 4; nf++) {
                const int nb = wn + nf*8 + ly;
                bf[nf][0] = Bs[nb][kb + lx];
                bf[nf][1] = Bs[nb][kb + lx + 4];
            }
#pragma unroll
            for (int mf = 0; mf < 4; mf++)
#pragma unroll
                for (int nf = 0; nf < 4; nf++)
                    mma_tf32(acc[mf][nf], af[mf], bf[nf]);
        }
        __syncthreads();
    }

#pragma unroll
    for (int nf = 0; nf < 4; nf++) {
        const int gn = n0c + wn + nf*8 + lx*2;
        const float2 bv = *(const float2*)&bias[gn];
#pragma unroll
        for (int mf = 0; mf < 4; mf++) {
            const int gm0 = m0c + wm + mf*16 + ly;
            float2 o0, o1;
            o0.x = fmaxf(acc[mf][nf][0] + bv.x, 0.f);
            o0.y = fmaxf(acc[mf][nf][1] + bv.y, 0.f);
            o1.x = fmaxf(acc[mf][nf][2] + bv.x, 0.f);
            o1.y = fmaxf(acc[mf][nf][3] + bv.y, 0.f);
            *(float2*)&g_C1[(size_t)gm0*NS + gn]       = o0;
            *(float2*)&g_C1[(size_t)(gm0+8)*NS + gn]   = o1;
        }
    }

    // publish this 128-row C1 block (2 producers per block)
    __syncthreads();
    if (tid == 0) {
        asm volatile("fence.acq_rel.gpu;" ::: "memory");
        atomicAdd(&g_c1flag[blockIdx.y], 1u);
    }
}

__global__ __launch_bounds__(256, 2) void gemm2_kernel(
    const float* __restrict__ W,     // [ND][NS]
    const float* __restrict__ bias)  // [ND]
{
    __shared__ __align__(16) uint32_t As[128][36];
    __shared__ __align__(16) uint32_t Bs[128][36];

    const int tid  = threadIdx.x;
    const int warp = tid >> 5;
    const int lane = tid & 31;
    const int m0c  = blockIdx.y * 128;
    const int n0c  = blockIdx.x * 128;

    // wait for our C1 block (both gemm1 producers)
    if (tid == 0) {
        while (ld_acquire_gpu(&g_c1flag[blockIdx.y]) < 2u) { }
    }
    __syncthreads();

    const int row = tid >> 1;
    const int kq  = tid & 1;

    const float* arow = g_C1 + (size_t)(m0c + row) * NS;
    const float* brow = W    + (size_t)(n0c + row) * NS;

    const int wm = (warp & 1) * 64;
    const int wn = (warp >> 1) * 32;
    const int ly = lane >> 2;
    const int lx = lane & 3;

    float acc[4][4][4] = {};

    float4 pa[4], pb[4];
#pragma unroll
    for (int q = 0; q < 4; q++) {
        pa[q] = *(const float4*)&arow[kq*16 + q*4];
        pb[q] = *(const float4*)&brow[kq*16 + q*4];
    }

    for (int k0 = 0; k0 < NS; k0 += 32) {
#pragma unroll
        for (int q = 0; q < 4; q++) {
            const int c = kq*16 + q*4;
            *(uint4*)&As[row][c] = make_uint4(f2tf(pa[q].x), f2tf(pa[q].y), f2tf(pa[q].z), f2tf(pa[q].w));
            *(uint4*)&Bs[row][c] = make_uint4(f2tf(pb[q].x), f2tf(pb[q].y), f2tf(pb[q].z), f2tf(pb[q].w));
        }
        __syncthreads();
        if (k0 + 32 < NS) {
#pragma unroll
            for (int q = 0; q < 4; q++) {
                pa[q] = *(const float4*)&arow[k0+32 + kq*16 + q*4];
                pb[q] = *(const float4*)&brow[k0+32 + kq*16 + q*4];
            }
        }
#pragma unroll
        for (int kk = 0; kk < 4; kk++) {
            const int kb = kk * 8;
            uint32_t af[4][4], bf[4][2];
#pragma unroll
            for (int mf = 0; mf < 4; mf++) {
                const int rb = wm + mf*16 + ly;
                af[mf][0] = As[rb    ][kb + lx];
                af[mf][1] = As[rb + 8][kb + lx];
                af[mf][2] = As[rb    ][kb + lx + 4];
                af[mf][3] = As[rb + 8][kb + lx + 4];
            }
#pragma unroll
            for (int nf = 0; nf < 4; nf++) {
                const int nb = wn + nf*8 + ly;
                bf[nf][0] = Bs[nb][kb + lx];
                bf[nf][1] = Bs[nb][kb + lx + 4];
            }
#pragma unroll
            for (int mf = 0; mf < 4; mf++)
#pragma unroll
                for (int nf = 0; nf < 4; nf++)
                    mma_tf32(acc[mf][nf], af[mf], bf[nf]);
        }
        __syncthreads();
    }

#pragma unroll
    for (int nf = 0; nf < 4; nf++) {
        const int gn = n0c + wn + nf*8 + lx*2;
        const float2 bv = *(const float2*)&bias[gn];
#pragma unroll
        for (int mf = 0; mf < 4; mf++) {
            const int gm0 = m0c + wm + mf*16 + ly;
            float2 o0, o1;
            o0.x = fmaxf(acc[mf][nf][0] + bv.x, 0.f);
            o0.y = fmaxf(acc[mf][nf][1] + bv.y, 0.f);
            o1.x = fmaxf(acc[mf][nf][2] + bv.x, 0.f);
            o1.y = fmaxf(acc[mf][nf][3] + bv.y, 0.f);
            *(float2*)&g_L[(size_t)gm0*ND + gn]       = o0;
            *(float2*)&g_L[(size_t)(gm0+8)*ND + gn]   = o1;
        }
    }
}

// ---------------------------------------------------------------------------
// Flag reset (graph replays reuse state; must precede everything)
// ---------------------------------------------------------------------------
__global__ void init_bar_kernel()
{
    const int i = threadIdx.x;            // 256 threads
    if (i < 16) g_flag[i] = 0u;
    g_c1flag[i] = 0u;
}

// ---------------------------------------------------------------------------
// Persistent recurrent kernel (R13 structure — measured best, byte-identical).
// 128 CTAs = 16 m-chains x 8 n-blocks; CTA tile 16(M) x 64(N), K=512.
// 8 warps, each 16m x 8n. bf16x2 split mma + ldmatrix; single fp32 accumulator.
// Publish: stcg stores -> __syncthreads -> tid0 {fence.acq_rel.gpu; relaxed
// atomic} (scope promotion via the barrier). Consume: ld.acquire poll.
// ---------------------------------------------------------------------------
__global__ __launch_bounds__(256, 1) void step_persist(
    const float* __restrict__ Wh,     // [ND][ND]
    const float* __restrict__ bhid)   // [ND]
{
    extern __shared__ uint32_t smu[]; // bf16 PAIRS, row stride PROW
    uint32_t* Ws0 = smu;              // [64][PROW] W main
    uint32_t* Ws1 = smu + 64*PROW;    // [64][PROW] W residual
    uint32_t* hs0 = smu + 128*PROW;   // [16][PROW] h main
    uint32_t* hs1 = smu + 144*PROW;   // [16][PROW] h residual

    const int tid  = threadIdx.x;
    const int bx   = blockIdx.x;
    const int mb   = bx >> 3;          // 0..15 (m-chain)
    const int m0   = mb * 16;
    const int n0   = (bx & 7) * 64;
    const int warp = tid >> 5;
    const int lane = tid & 31;
    const int wn   = warp * 8;
    const int ly   = lane >> 2;
    const int lx   = lane & 3;

    // --- split W slice [64n][512k] into bf16 hi/lo pairs in smem (once) ---
#pragma unroll
    for (int i = 0; i < 64; i++) {
        const int idx = tid + i*256;        // 0..16383 pair slots (64 rows x 256)
        const int r   = idx >> 8;
        const int p   = idx & 255;          // pair col (2 k values)
        float2 w = *(const float2*)&Wh[(size_t)(n0+r)*ND + p*2];
        __nv_bfloat16 h0x = __float2bfloat16_rn(w.x);
        __nv_bfloat16 h0y = __float2bfloat16_rn(w.y);
        float rx = w.x - __bfloat162float(h0x);
        float ry = w.y - __bfloat162float(h0y);
        __nv_bfloat162 p0; p0.x = h0x; p0.y = h0y;
        __nv_bfloat162 p1; p1.x = __float2bfloat16_rn(rx); p1.y = __float2bfloat16_rn(ry);
        Ws0[r*PROW + p] = *(uint32_t*)&p0;
        Ws1[r*PROW + p] = *(uint32_t*)&p1;
    }
    const int gnc = n0 + wn + lx*2;
    const float bb0 = bhid[gnc];
    const float bb1 = bhid[gnc + 1];
    const int gm0 = m0 + ly;               // epilogue rows gm0, gm0+8

    // per-lane ldmatrix base addresses (bytes, shared space)
    const uint32_t aOff = (uint32_t)((lane & 15) * PROW * 4 + (lane >> 4) * 16);
    const uint32_t aHi  = smem_u32(hs0) + aOff;
    const uint32_t aLo  = smem_u32(hs1) + aOff;
    const uint32_t bOff = (uint32_t)((wn + (lane & 7)) * PROW * 4 + (lane >> 3) * 16);
    const uint32_t bHi  = smem_u32(Ws0) + bOff;
    const uint32_t bLo  = smem_u32(Ws1) + bOff;

    __syncthreads();

    // prefetch L for t=0
    float2 l0 = __ldg((const float2*)&g_L[(size_t)gm0*ND + gnc]);
    float2 l1 = __ldg((const float2*)&g_L[(size_t)(gm0+8)*ND + gnc]);

    for (int t = 0; t < NT; t++) {
        __nv_bfloat16* __restrict__ ho0 = g_h0[(t+1) & 1];
        __nv_bfloat16* __restrict__ ho1 = g_h1[(t+1) & 1];

        float acc[4] = {0.f, 0.f, 0.f, 0.f};
        if (t > 0) {
            const __nv_bfloat16* __restrict__ hi0 = g_h0[t & 1];
            const __nv_bfloat16* __restrict__ hi1 = g_h1[t & 1];

            // wait for the 8 producers of this m-chain (step t's h ready)
            if (tid == 0) {
                const unsigned target = (unsigned)t * 8u;
                while (ld_acquire_gpu(&g_flag[mb]) < target) { }
            }
            __syncthreads();

            // stage h tiles: 16 rows x 64 uint4 each array (16KB each)
#pragma unroll
            for (int i = 0; i < 4; i++) {
                const int idx = tid + i*256;   // 0..1023
                const int r   = idx >> 6;      // 0..15
                const int c4  = idx & 63;      // 0..63
                uint4 v = __ldcg((const uint4*)(hi0 + (size_t)(m0+r)*ND) + c4);
                *(uint4*)&hs0[r*PROW + c4*4] = v;
            }
#pragma unroll
            for (int i = 0; i < 4; i++) {
                const int idx = tid + i*256;
                const int r   = idx >> 6;
                const int c4  = idx & 63;
                uint4 v = __ldcg((const uint4*)(hi1 + (size_t)(m0+r)*ND) + c4);
                *(uint4*)&hs1[r*PROW + c4*4] = v;
            }
            __syncthreads();

#pragma unroll 4
            for (int kc = 0; kc < 16; kc++) {  // k32 chunks
                const uint32_t off = kc * 64;  // 32 bf16 = 64 bytes
                uint32_t ah0[4], ah1[4], al0[4], al1[4], bh[4], bl[4];
                ldsm_x4(ah0, aHi + off);
                ldsm_x4(ah1, aHi + off + 32);
                ldsm_x4(al0, aLo + off);
                ldsm_x4(al1, aLo + off + 32);
                ldsm_x4(bh,  bHi + off);
                ldsm_x4(bl,  bLo + off);
                mma_bf16(acc, ah0, &bh[0]);    // main, chunk 0
                mma_bf16(acc, al0, &bh[0]);    // h residual
                mma_bf16(acc, ah0, &bl[0]);    // W residual
                mma_bf16(acc, ah1, &bh[2]);    // main, chunk 1
                mma_bf16(acc, al1, &bh[2]);
                mma_bf16(acc, ah1, &bl[2]);
            }
        }

        // epilogue: +L +bias, tanh, split to bf16 pair, store via stcg
        {
            float o00 = tanhf(acc[0] + l0.x + bb0);
            float o01 = tanhf(acc[1] + l0.y + bb1);
            float o10 = tanhf(acc[2] + l1.x + bb0);
            float o11 = tanhf(acc[3] + l1.y + bb1);

            __nv_bfloat162 h00, h01, r00, r01;
            h00.x = __float2bfloat16_rn(o00);
            h00.y = __float2bfloat16_rn(o01);
            r00.x = __float2bfloat16_rn(o00 - __bfloat162float(h00.x));
            r00.y = __float2bfloat16_rn(o01 - __bfloat162float(h00.y));
            h01.x = __float2bfloat16_rn(o10);
            h01.y = __float2bfloat16_rn(o11);
            r01.x = __float2bfloat16_rn(o10 - __bfloat162float(h01.x));
            r01.y = __float2bfloat16_rn(o11 - __bfloat162float(h01.y));

            __stcg((uint32_t*)&ho0[(size_t)gm0*ND + gnc],     *(uint32_t*)&h00);
            __stcg((uint32_t*)&ho1[(size_t)gm0*ND + gnc],     *(uint32_t*)&r00);
            __stcg((uint32_t*)&ho0[(size_t)(gm0+8)*ND + gnc], *(uint32_t*)&h01);
            __stcg((uint32_t*)&ho1[(size_t)(gm0+8)*ND + gnc], *(uint32_t*)&r01);
        }

        // prefetch L for t+1 (hides L2 latency under the arrive + next wait)
        if (t + 1 < NT) {
            const float* __restrict__ Ln = g_L + (size_t)(t+1) * NB * ND;
            l0 = __ldg((const float2*)&Ln[(size_t)gm0*ND + gnc]);
            l1 = __ldg((const float2*)&Ln[(size_t)(gm0+8)*ND + gnc]);
        }

        // publish: barrier gives CTA-scope happens-before into tid0; tid0's
        // gpu-scope fence promotes all threads' stores, then relaxed arrival
        __syncthreads();
        if (tid == 0) {
            asm volatile("fence.acq_rel.gpu;" ::: "memory");
            atomicAdd(&g_flag[mb], 1u);
        }
    }
}

// ---------------------------------------------------------------------------
// Row L2-normalize final h (split arrays, index 0 after even NT)
// ---------------------------------------------------------------------------
__global__ __launch_bounds__(128) void norm_kernel(float* __restrict__ out)
{
    __shared__ float red[4];
    const int row = blockIdx.x;
    const int tid = threadIdx.x;   // each covers 4 cols

    const __nv_bfloat162* h0 = (const __nv_bfloat162*)(g_h0[0] + (size_t)row * ND);
    const __nv_bfloat162* h1 = (const __nv_bfloat162*)(g_h1[0] + (size_t)row * ND);
    __nv_bfloat162 a0 = h0[tid*2], a1 = h0[tid*2+1];
    __nv_bfloat162 b0 = h1[tid*2], b1 = h1[tid*2+1];
    float4 v;
    v.x = __bfloat162float(a0.x) + __bfloat162float(b0.x);
    v.y = __bfloat162float(a0.y) + __bfloat162float(b0.y);
    v.z = __bfloat162float(a1.x) + __bfloat162float(b1.x);
    v.w = __bfloat162float(a1.y) + __bfloat162float(b1.y);

    float s = v.x*v.x + v.y*v.y + v.z*v.z + v.w*v.w;
#pragma unroll
    for (int o = 16; o; o >>= 1) s += __shfl_xor_sync(0xFFFFFFFFu, s, o);
    if ((tid & 31) == 0) red[tid >> 5] = s;
    __syncthreads();
    const float tot = red[0] + red[1] + red[2] + red[3];
    const float inv = 1.f / fmaxf(sqrtf(tot), 1e-12f);
    float4 o4 = make_float4(v.x*inv, v.y*inv, v.z*inv, v.w*inv);
    *(float4*)&out[(size_t)row * ND + tid * 4] = o4;
}

// ---------------------------------------------------------------------------
// Launch: init -> gemm1 (PDL trigger) -> gemm2 (PDL dependent) -> step -> norm
// Only the two FF GEMMs overlap; step_persist is a normal launch and keeps
// its measured-best R13 profile. c1 flags make the overlap safe even if PDL
// degenerates to serial execution.
// ---------------------------------------------------------------------------
extern "C" void kernel_launch(void* const* d_in, const int* in_sizes, int n_in,
                              void* d_out, int out_size)
{
    const int*   x     = (const int*)  d_in[0];
    const float* emb   = (const float*)d_in[1];
    const float* W_inp = (const float*)d_in[2];
    const float* b_inp = (const float*)d_in[3];
    const float* W_mid = (const float*)d_in[4];
    const float* b_mid = (const float*)d_in[5];
    const float* W_hid = (const float*)d_in[6];
    const float* b_hid = (const float*)d_in[7];
    float* out = (float*)d_out;

    cudaFuncSetAttribute(step_persist, cudaFuncAttributeMaxDynamicSharedMemorySize, STEP_SMEM);

    init_bar_kernel<<<1, 256>>>();
    gemm1_kernel<<<dim3(NS/128, NM/128), 256>>>(x, emb, W_inp, b_inp);

    // gemm2: programmatic dependent launch after gemm1 (overlaps tail of gemm1)
    {
        cudaLaunchConfig_t cfg = {};
        cfg.gridDim  = dim3(ND/128, NM/128);
        cfg.blockDim = dim3(256);
        cfg.dynamicSmemBytes = 0;
        cfg.stream = 0;
        cudaLaunchAttribute attr[1];
        attr[0].id = cudaLaunchAttributeProgrammaticStreamSerialization;
        attr[0].val.programmaticStreamSerializationAllowed = 1;
        cfg.attrs = attr;
        cfg.numAttrs = 1;
        cudaLaunchKernelEx(&cfg, gemm2_kernel, W_mid, b_mid);
    }

    // Recurrence: normal launch (R13 profile), per-chain flags
    step_persist<<<SGRID, 256, STEP_SMEM>>>(W_hid, b_hid);

    norm_kernel<<<NB, 128>>>(out);
}